// round 14
// baseline (speedup 1.0000x reference)
#include <cuda_runtime.h>
#include <cuda_fp16.h>
#include <cstdint>

// ============================================================================
// out[8192,4096] = x[8192,4096] @ ternary(W)^T[4096,4096] + bias
// cp.async + ldmatrix + mma.sync m16n8k16 fp16->fp32 (baseline sm_100 PTX).
// R13 (resubmit after infra failure): spread cp.async issue across k16 steps
// 0-3 (was one 24-op burst at step 0) to kill MIO/LSU contention with
// ldmatrix; bias staged to smem; skip dead final-iteration wait.
// ============================================================================
#define M_TOTAL 8192
#define N_TOTAL 4096
#define K_TOTAL 4096

__device__ __half g_xh[(size_t)M_TOTAL * K_TOTAL];
__device__ __half g_wq[(size_t)N_TOTAL * K_TOTAL];

// ============================================================================
// Fused prep: blocks [0, 4096) ternary-quantize W rows -> fp16 {-1,0,1};
//             blocks [4096, ...) convert x fp32 -> fp16 (2x float4 / thread).
// ============================================================================
__global__ void __launch_bounds__(256) prep_kernel(const float* __restrict__ w,
                                                   uint2* __restrict__ wq,
                                                   const float4* __restrict__ x4,
                                                   uint2* __restrict__ xh) {
    if (blockIdx.x < N_TOTAL) {
        const int row = blockIdx.x;
        const float4* wr = reinterpret_cast<const float4*>(w + (size_t)row * K_TOTAL);
        float4 v[4];
        float s = 0.f;
#pragma unroll
        for (int i = 0; i < 4; ++i) {
            v[i] = __ldcs(wr + threadIdx.x + i * 256);   // read-once: evict-first
            s += fabsf(v[i].x) + fabsf(v[i].y) + fabsf(v[i].z) + fabsf(v[i].w);
        }
#pragma unroll
        for (int o = 16; o; o >>= 1) s += __shfl_xor_sync(0xffffffffu, s, o);
        __shared__ float warp_sums[8];
        if ((threadIdx.x & 31) == 0) warp_sums[threadIdx.x >> 5] = s;
        __syncthreads();
        float tot = 0.f;
#pragma unroll
        for (int i = 0; i < 8; ++i) tot += warp_sums[i];
        const float t = 0.7f * (tot * (1.0f / (float)K_TOTAL));

        uint2* wo = wq + (size_t)row * (K_TOTAL / 4);
#pragma unroll
        for (int i = 0; i < 4; ++i) {
            const int idx = threadIdx.x + i * 256;
            float q0 = v[i].x > t ? 1.f : (v[i].x < -t ? -1.f : 0.f);
            float q1 = v[i].y > t ? 1.f : (v[i].y < -t ? -1.f : 0.f);
            float q2 = v[i].z > t ? 1.f : (v[i].z < -t ? -1.f : 0.f);
            float q3 = v[i].w > t ? 1.f : (v[i].w < -t ? -1.f : 0.f);
            __half2 p0 = __floats2half2_rn(q0, q1);
            __half2 p1 = __floats2half2_rn(q2, q3);
            uint2 u;
            u.x = *reinterpret_cast<uint32_t*>(&p0);
            u.y = *reinterpret_cast<uint32_t*>(&p1);
            wo[idx] = u;
        }
    } else {
        // 2 independent float4 per thread: 32B read (evict-first), 16B write
        const size_t i0 = (size_t)(blockIdx.x - N_TOTAL) * 512 + threadIdx.x;
        float4 va = __ldcs(x4 + i0);
        float4 vb = __ldcs(x4 + i0 + 256);
        __half2 a0 = __floats2half2_rn(va.x, va.y);
        __half2 a1 = __floats2half2_rn(va.z, va.w);
        __half2 b0 = __floats2half2_rn(vb.x, vb.y);
        __half2 b1 = __floats2half2_rn(vb.z, vb.w);
        uint2 ua, ub;
        ua.x = *reinterpret_cast<uint32_t*>(&a0);
        ua.y = *reinterpret_cast<uint32_t*>(&a1);
        ub.x = *reinterpret_cast<uint32_t*>(&b0);
        ub.y = *reinterpret_cast<uint32_t*>(&b1);
        xh[i0]       = ua;
        xh[i0 + 256] = ub;
    }
}

// ============================================================================
// GEMM: 128x256 CTA tile, BK=128 (two 64-k sub-blocks), 2-stage pipeline,
// 8 warps (2x4), warp tile 64x64, mma.sync m16n8k16 fp16 -> fp32 accum.
// Stage loads issued in 4 chunks across k16 steps 0-3 (MIO smoothing).
// ============================================================================
constexpr int BM = 128, BN = 256, BK = 128;
constexpr int K_ITERS = K_TOTAL / BK;               // 32
constexpr int A_SUB = BM * 64 * 2;                  // 16384
constexpr int B_SUB = BN * 64 * 2;                  // 32768
constexpr int B0_OFF = 2 * A_SUB;                   // 32768
constexpr int STAGE_BYTES = 2 * A_SUB + 2 * B_SUB;  // 98304
constexpr int BIAS_OFF = 2 * STAGE_BYTES;           // 196608
constexpr int SMEM_BYTES = BIAS_OFF + BN * 4;       // 197632

__device__ __forceinline__ void cp16(uint32_t s, const void* g) {
    asm volatile("cp.async.cg.shared.global [%0], [%1], 16;" :: "r"(s), "l"(g));
}
__device__ __forceinline__ void ldsm4(uint32_t* d, uint32_t a) {
    asm volatile("ldmatrix.sync.aligned.m8n8.x4.shared.b16 {%0,%1,%2,%3}, [%4];"
                 : "=r"(d[0]), "=r"(d[1]), "=r"(d[2]), "=r"(d[3]) : "r"(a));
}
__device__ __forceinline__ void mma16816(float* c, const uint32_t* a,
                                         uint32_t b0, uint32_t b1) {
    asm volatile(
        "mma.sync.aligned.m16n8k16.row.col.f32.f16.f16.f32 "
        "{%0,%1,%2,%3}, {%4,%5,%6,%7}, {%8,%9}, {%0,%1,%2,%3};"
        : "+f"(c[0]), "+f"(c[1]), "+f"(c[2]), "+f"(c[3])
        : "r"(a[0]), "r"(a[1]), "r"(a[2]), "r"(a[3]), "r"(b0), "r"(b1));
}

__global__ void __launch_bounds__(256, 1) ternary_gemm_kernel(
    const __half* __restrict__ xh,
    const __half* __restrict__ wq,
    const float* __restrict__ bias,
    float* __restrict__ out)
{
    extern __shared__ __align__(1024) char smem[];
    const uint32_t sb = (uint32_t)__cvta_generic_to_shared(smem);
    const int tid = threadIdx.x;
    const int wid = tid >> 5;
    const int lid = tid & 31;
    const int warp_m = wid & 1;
    const int warp_n = wid >> 1;
    const int m0 = blockIdx.y * BM;
    const int n0 = blockIdx.x * BN;

    // one quarter of a 128-k stage: 2 (of 8) A chunks + 4 (of 16) B chunks
    auto load_chunk = [&](int slot, int k0, int chunk) {
        const uint32_t base = sb + slot * STAGE_BYTES;
#pragma unroll
        for (int j = 0; j < 2; ++j) {
            const int i = chunk * 2 + j;          // 0..7
            const int sub = i >> 2, ii = i & 3;
            const int c = tid + ii * 256, row = c >> 3, ch = c & 7;
            cp16(base + sub * A_SUB + row * 128 + ((ch ^ (row & 7)) << 4),
                 xh + (size_t)(m0 + row) * K_TOTAL + k0 + sub * 64 + ch * 8);
        }
#pragma unroll
        for (int j = 0; j < 4; ++j) {
            const int i = chunk * 4 + j;          // 0..15
            const int sub = i >> 3, ii = i & 7;
            const int c = tid + ii * 256, row = c >> 3, ch = c & 7;
            cp16(base + B0_OFF + sub * B_SUB + row * 128 + ((ch ^ (row & 7)) << 4),
                 wq + (size_t)(n0 + row) * K_TOTAL + k0 + sub * 64 + ch * 8);
        }
    };

    float acc[4][8][4];
#pragma unroll
    for (int i = 0; i < 4; ++i)
#pragma unroll
        for (int j = 0; j < 8; ++j)
#pragma unroll
            for (int r = 0; r < 4; ++r) acc[i][j][r] = 0.f;

    // lane-constant address pieces (swizzle phase = lid&7)
    const uint32_t sw   = lid & 7;
    const uint32_t aoff = (warp_m * 64 + (lid & 15)) * 128;
    const uint32_t acb  = (uint32_t)(lid >> 4);
    const uint32_t boff = (warp_n * 64 + ((lid >> 4) << 3) + (lid & 7)) * 128;
    const uint32_t bcb  = (lid >> 3) & 1;

    uint32_t afr[2][4][4], bfr[2][4][4];

    // frag load for k16 index kn (0..7) within the 128-k stage at st
    auto ld_frags = [&](uint32_t st, int bi, int kn) {
        const uint32_t a_base = st + (kn >> 2) * A_SUB;
        const uint32_t b_base = st + B0_OFF + (kn >> 2) * B_SUB;
        const int kk = kn & 3;
#pragma unroll
        for (int p = 0; p < 4; ++p)
            ldsm4(bfr[bi][p], b_base + boff + p * 2048 + (((bcb + 2 * kk) ^ sw) << 4));
#pragma unroll
        for (int mt = 0; mt < 4; ++mt)
            ldsm4(afr[bi][mt], a_base + aoff + mt * 2048 + (((acb + 2 * kk) ^ sw) << 4));
    };
    auto do_mma = [&](int bi) {
#pragma unroll
        for (int mt = 0; mt < 4; ++mt)
#pragma unroll
            for (int nt = 0; nt < 8; ++nt)
                mma16816(acc[mt][nt], afr[bi][mt],
                         bfr[bi][nt >> 1][(nt & 1) * 2],
                         bfr[bi][nt >> 1][(nt & 1) * 2 + 1]);
    };

    // ---- prologue: full stage-0 load, bias -> smem, wait, first frags ----
#pragma unroll
    for (int c = 0; c < 4; ++c) load_chunk(0, 0, c);
    asm volatile("cp.async.commit_group;" ::: "memory");
    if (tid < BN / 4)
        reinterpret_cast<float4*>(smem + BIAS_OFF)[tid] =
            reinterpret_cast<const float4*>(bias + n0)[tid];
    asm volatile("cp.async.wait_group 0;" ::: "memory");
    __syncthreads();
    ld_frags(sb, 0, 0);

    // ---- mainloop: 32 iters of 8 k16 steps; barrier once per 128 k ----
    for (int it = 0; it < K_ITERS; ++it) {
        const uint32_t st  = sb + (it & 1) * STAGE_BYTES;
        const uint32_t stn = sb + ((it + 1) & 1) * STAGE_BYTES;
        const bool more = (it + 1 < K_ITERS);
#pragma unroll
        for (int k16 = 0; k16 < 8; ++k16) {
            const int cur = k16 & 1, nxt = cur ^ 1;
            if (k16 == 7) {
                if (more) {
                    // loads committed at k16==3 (~2000 cyc of flight) done;
                    // barrier closes the written slot's read window
                    asm volatile("cp.async.wait_group 0;" ::: "memory");
                    __syncthreads();
                    ld_frags(stn, nxt, 0);
                }
            } else {
                ld_frags(st, nxt, k16 + 1);
            }
            if (k16 < 4 && more) {
                load_chunk((it + 1) & 1, (it + 1) * BK, k16);
                if (k16 == 3)
                    asm volatile("cp.async.commit_group;" ::: "memory");
            }
            do_mma(cur);
        }
    }

    // ---- epilogue: bias (from smem) add + float2 stores ----
    const int g = lid >> 2, t = lid & 3;
#pragma unroll
    for (int mt = 0; mt < 4; ++mt) {
        const int row = m0 + warp_m * 64 + mt * 16 + g;
        float* o0 = out + (size_t)row * N_TOTAL;
        float* o1 = out + (size_t)(row + 8) * N_TOTAL;
#pragma unroll
        for (int nt = 0; nt < 8; ++nt) {
            const int col = n0 + warp_n * 64 + nt * 8 + 2 * t;
            const float2 bv = *reinterpret_cast<const float2*>(
                smem + BIAS_OFF + (size_t)(col - n0) * 4);
            float2 v0 = {acc[mt][nt][0] + bv.x, acc[mt][nt][1] + bv.y};
            float2 v1 = {acc[mt][nt][2] + bv.x, acc[mt][nt][3] + bv.y};
            *reinterpret_cast<float2*>(o0 + col) = v0;
            *reinterpret_cast<float2*>(o1 + col) = v1;
        }
    }
}

// ============================================================================
// Host launcher
// ============================================================================
extern "C" void kernel_launch(void* const* d_in, const int* in_sizes, int n_in,
                              void* d_out, int out_size) {
    const float* x    = (const float*)d_in[0];
    const float* w    = (const float*)d_in[1];
    const float* bias = (const float*)d_in[2];
    float* out        = (float*)d_out;

    void *xh, *wq;
    cudaGetSymbolAddress(&xh, g_xh);
    cudaGetSymbolAddress(&wq, g_wq);

    const int conv_blocks = (int)(((size_t)M_TOTAL * K_TOTAL) / (8 * 256));
    prep_kernel<<<N_TOTAL + conv_blocks, 256>>>(w, (uint2*)wq,
                                                (const float4*)x, (uint2*)xh);

    cudaFuncSetAttribute(ternary_gemm_kernel,
                         cudaFuncAttributeMaxDynamicSharedMemorySize, SMEM_BYTES);
    dim3 grid(N_TOTAL / BN, M_TOTAL / BM);
    ternary_gemm_kernel<<<grid, 256, SMEM_BYTES>>>(
        (const __half*)xh, (const __half*)wq, bias, out);
}

// round 17
// speedup vs baseline: 1.0273x; 1.0273x over previous
#include <cuda_runtime.h>
#include <cuda_fp16.h>
#include <cstdint>

// ============================================================================
// out[8192,4096] = x[8192,4096] @ ternary(W)^T[4096,4096] + bias
// cp.async + ldmatrix + mma.sync m16n8k16 fp16->fp32 (baseline sm_100 PTX).
// FINAL (R12 champion, resubmitted through broker infra failures):
// 128x256 CTA tile, BK=128 (two 64-k sub-blocks), 2-stage cp.async pipeline
// with cross-stage fragment prefetch, 8 warps (2x4), warp tile 64x64.
// Prep vectorized with __ldcs evict-first reads.
// Measured in R12: 610.6 us e2e, rel_err 2.08e-4, tensor pipe 87.1%.
// ============================================================================
#define M_TOTAL 8192
#define N_TOTAL 4096
#define K_TOTAL 4096

__device__ __half g_xh[(size_t)M_TOTAL * K_TOTAL];
__device__ __half g_wq[(size_t)N_TOTAL * K_TOTAL];

// ============================================================================
// Fused prep: blocks [0, 4096) ternary-quantize W rows -> fp16 {-1,0,1};
//             blocks [4096, ...) convert x fp32 -> fp16 (2x float4 / thread).
// ============================================================================
__global__ void __launch_bounds__(256) prep_kernel(const float* __restrict__ w,
                                                   uint2* __restrict__ wq,
                                                   const float4* __restrict__ x4,
                                                   uint2* __restrict__ xh) {
    if (blockIdx.x < N_TOTAL) {
        const int row = blockIdx.x;
        const float4* wr = reinterpret_cast<const float4*>(w + (size_t)row * K_TOTAL);
        float4 v[4];
        float s = 0.f;
#pragma unroll
        for (int i = 0; i < 4; ++i) {
            v[i] = __ldcs(wr + threadIdx.x + i * 256);   // read-once: evict-first
            s += fabsf(v[i].x) + fabsf(v[i].y) + fabsf(v[i].z) + fabsf(v[i].w);
        }
#pragma unroll
        for (int o = 16; o; o >>= 1) s += __shfl_xor_sync(0xffffffffu, s, o);
        __shared__ float warp_sums[8];
        if ((threadIdx.x & 31) == 0) warp_sums[threadIdx.x >> 5] = s;
        __syncthreads();
        float tot = 0.f;
#pragma unroll
        for (int i = 0; i < 8; ++i) tot += warp_sums[i];
        const float t = 0.7f * (tot * (1.0f / (float)K_TOTAL));

        uint2* wo = wq + (size_t)row * (K_TOTAL / 4);
#pragma unroll
        for (int i = 0; i < 4; ++i) {
            const int idx = threadIdx.x + i * 256;
            float q0 = v[i].x > t ? 1.f : (v[i].x < -t ? -1.f : 0.f);
            float q1 = v[i].y > t ? 1.f : (v[i].y < -t ? -1.f : 0.f);
            float q2 = v[i].z > t ? 1.f : (v[i].z < -t ? -1.f : 0.f);
            float q3 = v[i].w > t ? 1.f : (v[i].w < -t ? -1.f : 0.f);
            __half2 p0 = __floats2half2_rn(q0, q1);
            __half2 p1 = __floats2half2_rn(q2, q3);
            uint2 u;
            u.x = *reinterpret_cast<uint32_t*>(&p0);
            u.y = *reinterpret_cast<uint32_t*>(&p1);
            wo[idx] = u;
        }
    } else {
        // 2 independent float4 per thread: 32B read (evict-first), 16B write
        const size_t i0 = (size_t)(blockIdx.x - N_TOTAL) * 512 + threadIdx.x;
        float4 va = __ldcs(x4 + i0);
        float4 vb = __ldcs(x4 + i0 + 256);
        __half2 a0 = __floats2half2_rn(va.x, va.y);
        __half2 a1 = __floats2half2_rn(va.z, va.w);
        __half2 b0 = __floats2half2_rn(vb.x, vb.y);
        __half2 b1 = __floats2half2_rn(vb.z, vb.w);
        uint2 ua, ub;
        ua.x = *reinterpret_cast<uint32_t*>(&a0);
        ua.y = *reinterpret_cast<uint32_t*>(&a1);
        ub.x = *reinterpret_cast<uint32_t*>(&b0);
        ub.y = *reinterpret_cast<uint32_t*>(&b1);
        xh[i0]       = ua;
        xh[i0 + 256] = ub;
    }
}

// ============================================================================
// GEMM: 128x256 CTA tile, BK=128 (two 64-k sub-blocks), 2-stage pipeline,
// 8 warps (2x4), warp tile 64x64, mma.sync m16n8k16 fp16 -> fp32 accum.
// ============================================================================
constexpr int BM = 128, BN = 256, BK = 128;
constexpr int K_ITERS = K_TOTAL / BK;               // 32
constexpr int A_SUB = BM * 64 * 2;                  // 16384
constexpr int B_SUB = BN * 64 * 2;                  // 32768
constexpr int B0_OFF = 2 * A_SUB;                   // 32768
constexpr int STAGE_BYTES = 2 * A_SUB + 2 * B_SUB;  // 98304
constexpr int SMEM_BYTES = 2 * STAGE_BYTES;         // 196608

__device__ __forceinline__ void cp16(uint32_t s, const void* g) {
    asm volatile("cp.async.cg.shared.global [%0], [%1], 16;" :: "r"(s), "l"(g));
}
__device__ __forceinline__ void ldsm4(uint32_t* d, uint32_t a) {
    asm volatile("ldmatrix.sync.aligned.m8n8.x4.shared.b16 {%0,%1,%2,%3}, [%4];"
                 : "=r"(d[0]), "=r"(d[1]), "=r"(d[2]), "=r"(d[3]) : "r"(a));
}
__device__ __forceinline__ void mma16816(float* c, const uint32_t* a,
                                         uint32_t b0, uint32_t b1) {
    asm volatile(
        "mma.sync.aligned.m16n8k16.row.col.f32.f16.f16.f32 "
        "{%0,%1,%2,%3}, {%4,%5,%6,%7}, {%8,%9}, {%0,%1,%2,%3};"
        : "+f"(c[0]), "+f"(c[1]), "+f"(c[2]), "+f"(c[3])
        : "r"(a[0]), "r"(a[1]), "r"(a[2]), "r"(a[3]), "r"(b0), "r"(b1));
}

__global__ void __launch_bounds__(256, 1) ternary_gemm_kernel(
    const __half* __restrict__ xh,
    const __half* __restrict__ wq,
    const float* __restrict__ bias,
    float* __restrict__ out)
{
    extern __shared__ __align__(1024) char smem[];
    const uint32_t sb = (uint32_t)__cvta_generic_to_shared(smem);
    const int tid = threadIdx.x;
    const int wid = tid >> 5;
    const int lid = tid & 31;
    const int warp_m = wid & 1;
    const int warp_n = wid >> 1;
    const int m0 = blockIdx.y * BM;
    const int n0 = blockIdx.x * BN;

    auto load_sub_a = [&](uint32_t base, int k0) {
#pragma unroll
        for (int i = 0; i < 4; ++i) {
            int c = tid + i * 256, row = c >> 3, ch = c & 7;
            cp16(base + row * 128 + ((ch ^ (row & 7)) << 4),
                 xh + (size_t)(m0 + row) * K_TOTAL + k0 + ch * 8);
        }
    };
    auto load_sub_b = [&](uint32_t base, int k0) {
#pragma unroll
        for (int i = 0; i < 8; ++i) {
            int c = tid + i * 256, row = c >> 3, ch = c & 7;
            cp16(base + row * 128 + ((ch ^ (row & 7)) << 4),
                 wq + (size_t)(n0 + row) * K_TOTAL + k0 + ch * 8);
        }
    };
    auto load_stage = [&](int slot, int k0) {
        const uint32_t base = sb + slot * STAGE_BYTES;
        load_sub_a(base, k0);
        load_sub_a(base + A_SUB, k0 + 64);
        load_sub_b(base + B0_OFF, k0);
        load_sub_b(base + B0_OFF + B_SUB, k0 + 64);
    };

    float acc[4][8][4];
#pragma unroll
    for (int i = 0; i < 4; ++i)
#pragma unroll
        for (int j = 0; j < 8; ++j)
#pragma unroll
            for (int r = 0; r < 4; ++r) acc[i][j][r] = 0.f;

    // lane-constant address pieces (swizzle phase = lid&7)
    const uint32_t sw   = lid & 7;
    const uint32_t aoff = (warp_m * 64 + (lid & 15)) * 128;
    const uint32_t acb  = (uint32_t)(lid >> 4);
    const uint32_t boff = (warp_n * 64 + ((lid >> 4) << 3) + (lid & 7)) * 128;
    const uint32_t bcb  = (lid >> 3) & 1;

    uint32_t afr[2][4][4], bfr[2][4][4];

    // frag load for k16 index kn (0..7) within the 128-k stage at st
    auto ld_frags = [&](uint32_t st, int bi, int kn) {
        const uint32_t a_base = st + (kn >> 2) * A_SUB;
        const uint32_t b_base = st + B0_OFF + (kn >> 2) * B_SUB;
        const int kk = kn & 3;
#pragma unroll
        for (int p = 0; p < 4; ++p)
            ldsm4(bfr[bi][p], b_base + boff + p * 2048 + (((bcb + 2 * kk) ^ sw) << 4));
#pragma unroll
        for (int mt = 0; mt < 4; ++mt)
            ldsm4(afr[bi][mt], a_base + aoff + mt * 2048 + (((acb + 2 * kk) ^ sw) << 4));
    };
    auto do_mma = [&](int bi) {
#pragma unroll
        for (int mt = 0; mt < 4; ++mt)
#pragma unroll
            for (int nt = 0; nt < 8; ++nt)
                mma16816(acc[mt][nt], afr[bi][mt],
                         bfr[bi][nt >> 1][(nt & 1) * 2],
                         bfr[bi][nt >> 1][(nt & 1) * 2 + 1]);
    };

    // ---- prologue: load stage 0, wait, preload first frags ----
    load_stage(0, 0);
    asm volatile("cp.async.commit_group;" ::: "memory");
    asm volatile("cp.async.wait_group 0;" ::: "memory");
    __syncthreads();
    ld_frags(sb, 0, 0);

    // ---- mainloop: 32 iters of 8 k16 steps; barrier once per 128 k ----
    for (int it = 0; it < K_ITERS; ++it) {
        const uint32_t st  = sb + (it & 1) * STAGE_BYTES;
        const uint32_t stn = sb + ((it + 1) & 1) * STAGE_BYTES;
#pragma unroll
        for (int k16 = 0; k16 < 8; ++k16) {
            const int cur = k16 & 1, nxt = cur ^ 1;
            if (k16 == 7) {
                // next stage's loads (committed at k16==0) are done; barrier
                // closes the written slot's read window; prefetch its frags
                asm volatile("cp.async.wait_group 0;" ::: "memory");
                __syncthreads();
                if (it + 1 < K_ITERS) ld_frags(stn, nxt, 0);
            } else {
                ld_frags(st, nxt, k16 + 1);
            }
            if (k16 == 0) {
                if (it + 1 < K_ITERS) load_stage((it + 1) & 1, (it + 1) * BK);
                asm volatile("cp.async.commit_group;" ::: "memory");
            }
            do_mma(cur);
        }
    }

    // ---- epilogue: bias add + float2 stores ----
    const int g = lid >> 2, t = lid & 3;
#pragma unroll
    for (int mt = 0; mt < 4; ++mt) {
        const int row = m0 + warp_m * 64 + mt * 16 + g;
        float* o0 = out + (size_t)row * N_TOTAL;
        float* o1 = out + (size_t)(row + 8) * N_TOTAL;
#pragma unroll
        for (int nt = 0; nt < 8; ++nt) {
            const int col = n0 + warp_n * 64 + nt * 8 + 2 * t;
            const float2 bv = *reinterpret_cast<const float2*>(bias + col);
            float2 v0 = {acc[mt][nt][0] + bv.x, acc[mt][nt][1] + bv.y};
            float2 v1 = {acc[mt][nt][2] + bv.x, acc[mt][nt][3] + bv.y};
            *reinterpret_cast<float2*>(o0 + col) = v0;
            *reinterpret_cast<float2*>(o1 + col) = v1;
        }
    }
}

// ============================================================================
// Host launcher
// ============================================================================
extern "C" void kernel_launch(void* const* d_in, const int* in_sizes, int n_in,
                              void* d_out, int out_size) {
    const float* x    = (const float*)d_in[0];
    const float* w    = (const float*)d_in[1];
    const float* bias = (const float*)d_in[2];
    float* out        = (float*)d_out;

    void *xh, *wq;
    cudaGetSymbolAddress(&xh, g_xh);
    cudaGetSymbolAddress(&wq, g_wq);

    const int conv_blocks = (int)(((size_t)M_TOTAL * K_TOTAL) / (8 * 256));
    prep_kernel<<<N_TOTAL + conv_blocks, 256>>>(w, (uint2*)wq,
                                                (const float4*)x, (uint2*)xh);

    cudaFuncSetAttribute(ternary_gemm_kernel,
                         cudaFuncAttributeMaxDynamicSharedMemorySize, SMEM_BYTES);
    dim3 grid(N_TOTAL / BN, M_TOTAL / BM);
    ternary_gemm_kernel<<<grid, 256, SMEM_BYTES>>>(
        (const __half*)xh, (const __half*)wq, bias, out);
}